// round 1
// baseline (speedup 1.0000x reference)
#include <cuda_runtime.h>

typedef unsigned long long ull;

// ---- packed f32x2 helpers (sm_100+ PTX) ----
__device__ __forceinline__ ull pk2(float lo, float hi) {
    ull r; asm("mov.b64 %0, {%1, %2};" : "=l"(r) : "f"(lo), "f"(hi)); return r;
}
__device__ __forceinline__ ull bc2(float v) { return pk2(v, v); }
__device__ __forceinline__ void upk2(ull r, float& lo, float& hi) {
    asm("mov.b64 {%0, %1}, %2;" : "=f"(lo), "=f"(hi) : "l"(r));
}
__device__ __forceinline__ ull fma2(ull a, ull b, ull c) {
    ull d; asm("fma.rn.f32x2 %0, %1, %2, %3;" : "=l"(d) : "l"(a), "l"(b), "l"(c)); return d;
}
__device__ __forceinline__ ull add2(ull a, ull b) {
    ull d; asm("add.rn.f32x2 %0, %1, %2;" : "=l"(d) : "l"(a), "l"(b)); return d;
}
__device__ __forceinline__ ull mul2(ull a, ull b) {
    ull d; asm("mul.rn.f32x2 %0, %1, %2;" : "=l"(d) : "l"(a), "l"(b)); return d;
}

// Shapes: b=4, c=16, m=8, h=w=64, O=64.
// Block: (lwg, lh, b). Covers pixel tile rows {2lh,2lh+1}, cols [8lwg, 8lwg+8).
// 256 threads = 64 o  x  4 superpixels (sp). Thread handles one (b,o,superpixel):
//   16 output channels x 4 pixels.
__global__ __launch_bounds__(256) void adapt_attn(
    const float* __restrict__ x,
    const float* __restrict__ wq,
    const float* __restrict__ wk,
    const float* __restrict__ wv,
    float* __restrict__ out)
{
    // x tile: [ch=16][m=8][pix], pix = hhi*8 + wwoff, row stride 20 floats,
    // ch stride 164 floats (pads chosen for conflict-free LDS.64/.128)
    __shared__ __align__(16) float xs[16 * 164];
    __shared__ ull wq_d[64][9];     // (0.125*wq, 0.125*wq) dup,  [o][m], pad to kill 4-way
    __shared__ ull wk_p[8][4][9];   // pairs over consecutive rows: [j2][o&3][m]
    __shared__ ull wv_d[16][4][9];  // dup: [j][o&3][m]

    const int t   = threadIdx.x;
    const int lwg = blockIdx.x;   // 0..7
    const int lh  = blockIdx.y;   // 0..31
    const int b   = blockIdx.z;   // 0..3

    // ---- stage x tile: 512 float4 ----
    {
        const int hh0 = 2 * lh, ww0 = 8 * lwg;
#pragma unroll
        for (int it = 0; it < 2; ++it) {
            int idx = t + it * 256;                 // 0..511
            int q   = idx & 1;
            int hhi = (idx >> 1) & 1;
            int m   = (idx >> 2) & 7;
            int ch  = idx >> 5;
            const float4 v = *reinterpret_cast<const float4*>(
                x + ((b * 16 + ch) * 8 + m) * 4096 + (hh0 + hhi) * 64 + ww0 + 4 * q);
            *reinterpret_cast<float4*>(&xs[ch * 164 + m * 20 + hhi * 8 + 4 * q]) = v;
        }
    }
    // ---- stage weights (duplicated / paired, packed) ----
    {
#pragma unroll
        for (int it = 0; it < 2; ++it) {
            int idx = t + it * 256;                 // 0..511 -> (row r, m)
            int m = idx & 7, r = idx >> 3;
            wq_d[r][m] = bc2(wq[idx] * 0.125f);     // fold scaling = h^-0.5 = 1/8
            wv_d[r & 15][r >> 4][m] = bc2(wv[idx]);
        }
        if (t < 256) {
            int m = t & 7, r2 = t >> 3;             // rows (2*r2, 2*r2+1)
            wk_p[r2 & 7][r2 >> 3][m] = pk2(wk[(2 * r2) * 8 + m], wk[(2 * r2 + 1) * 8 + m]);
        }
    }
    __syncthreads();

    const int sp = t & 3;         // superpixel within tile (lw = 4*lwg + sp)
    const int o  = t >> 2;        // 0..63
    const int ck = o >> 2;        // k/v channel
    const int oq = o & 3;         // selects 16-row group of wk/wv

    // ---- x for the k/v channel, packed over pixel pairs: A=(p0,p1), B=(p2,p3) ----
    const float* xck = &xs[ck * 164];
    ull xkA[8], xkB[8];
#pragma unroll
    for (int m = 0; m < 8; ++m) {
        xkA[m] = *reinterpret_cast<const ull*>(xck + m * 20 + 2 * sp);
        xkB[m] = *reinterpret_cast<const ull*>(xck + m * 20 + 8 + 2 * sp);
    }

    // ---- kq[j2][p]: packed over (j,j+1). 256 FFMA2 ----
    ull kq[8][4];
#pragma unroll
    for (int j2 = 0; j2 < 8; ++j2)
#pragma unroll
        for (int p = 0; p < 4; ++p) kq[j2][p] = 0ull;
#pragma unroll
    for (int m = 0; m < 8; ++m) {
        float a0, a1, b0, b1;
        upk2(xkA[m], a0, a1); upk2(xkB[m], b0, b1);
        ull xb0 = bc2(a0), xb1 = bc2(a1), xb2 = bc2(b0), xb3 = bc2(b1);
#pragma unroll
        for (int j2 = 0; j2 < 8; ++j2) {
            ull w = wk_p[j2][oq][m];
            kq[j2][0] = fma2(w, xb0, kq[j2][0]);
            kq[j2][1] = fma2(w, xb1, kq[j2][1]);
            kq[j2][2] = fma2(w, xb2, kq[j2][2]);
            kq[j2][3] = fma2(w, xb3, kq[j2][3]);
        }
    }

    // ---- vq[j]: packed over pixel pairs. 256 FFMA2 ----
    ull vqA[16], vqB[16];
#pragma unroll
    for (int j = 0; j < 16; ++j) { vqA[j] = 0ull; vqB[j] = 0ull; }
#pragma unroll
    for (int m = 0; m < 8; ++m) {
#pragma unroll
        for (int j = 0; j < 16; ++j) {
            ull w = wv_d[j][oq][m];
            vqA[j] = fma2(w, xkA[m], vqA[j]);
            vqB[j] = fma2(w, xkB[m], vqB[j]);
        }
    }

    ull wqv[8];
#pragma unroll
    for (int m = 0; m < 8; ++m) wqv[m] = wq_d[o][m];

    const ull eighth = bc2(0.125f);
    float* op = out + ((b * 16) * 64 + o) * 4096 + (2 * lh) * 64 + (8 * lwg + 2 * sp);

#pragma unroll 1
    for (int i = 0; i < 16; ++i) {
        const float* xr = &xs[i * 164];
        ull qvA = 0ull, qvB = 0ull, rsA = 0ull, rsB = 0ull;
#pragma unroll
        for (int m = 0; m < 8; ++m) {
            ull a = *reinterpret_cast<const ull*>(xr + m * 20 + 2 * sp);
            ull c = *reinterpret_cast<const ull*>(xr + m * 20 + 8 + 2 * sp);
            qvA = fma2(wqv[m], a, qvA);
            qvB = fma2(wqv[m], c, qvB);
            rsA = add2(rsA, a);     // residual: mean over m
            rsB = add2(rsB, c);
        }
        float q0, q1, q2, q3;
        upk2(qvA, q0, q1); upk2(qvB, q2, q3);
        ull qb0 = bc2(q0), qb1 = bc2(q1), qb2 = bc2(q2), qb3 = bc2(q3);

        float att[16];
#pragma unroll
        for (int j2 = 0; j2 < 8; ++j2) {
            ull acc = mul2(qb0, kq[j2][0]);
            acc = fma2(qb1, kq[j2][1], acc);
            acc = fma2(qb2, kq[j2][2], acc);
            acc = fma2(qb3, kq[j2][3], acc);
            upk2(acc, att[2 * j2], att[2 * j2 + 1]);
        }

        // tree max
        float mx4[4];
#pragma unroll
        for (int k = 0; k < 4; ++k)
            mx4[k] = fmaxf(fmaxf(att[4 * k], att[4 * k + 1]),
                           fmaxf(att[4 * k + 2], att[4 * k + 3]));
        float mx = fmaxf(fmaxf(mx4[0], mx4[1]), fmaxf(mx4[2], mx4[3]));

        float e[16];
#pragma unroll
        for (int j = 0; j < 16; ++j) e[j] = __expf(att[j] - mx);
        float s4[4];
#pragma unroll
        for (int k = 0; k < 4; ++k)
            s4[k] = (e[4 * k] + e[4 * k + 1]) + (e[4 * k + 2] + e[4 * k + 3]);
        float ssum = (s4[0] + s4[1]) + (s4[2] + s4[3]);
        float inv = __fdividef(1.0f, ssum);

        // out[p] = (sum_j e_j * v_j[p]) * inv + res[p]   (2-way split accumulators)
        ull oA0 = 0ull, oA1 = 0ull, oB0 = 0ull, oB1 = 0ull;
#pragma unroll
        for (int j = 0; j < 8; ++j) {
            ull eb0 = bc2(e[j]);
            ull eb1 = bc2(e[j + 8]);
            oA0 = fma2(eb0, vqA[j], oA0);
            oA1 = fma2(eb1, vqA[j + 8], oA1);
            oB0 = fma2(eb0, vqB[j], oB0);
            oB1 = fma2(eb1, vqB[j + 8], oB1);
        }
        ull invb = bc2(inv);
        ull fA = fma2(add2(oA0, oA1), invb, mul2(rsA, eighth));
        ull fB = fma2(add2(oB0, oB1), invb, mul2(rsB, eighth));

        *reinterpret_cast<ull*>(op)      = fA;   // row hh = 2lh   (p0,p1)
        *reinterpret_cast<ull*>(op + 64) = fB;   // row hh = 2lh+1 (p2,p3)
        op += 64 * 4096;                          // next output channel i
    }
}

extern "C" void kernel_launch(void* const* d_in, const int* in_sizes, int n_in,
                              void* d_out, int out_size) {
    const float* x  = (const float*)d_in[0];
    const float* wq = (const float*)d_in[1];
    const float* wk = (const float*)d_in[2];
    const float* wv = (const float*)d_in[3];
    // d_in[4] (w_p) is provably unused: the positional term is constant across the
    // softmax axis and cancels exactly.
    dim3 grid(8, 32, 4);   // (lwg, lh, b)
    adapt_attn<<<grid, 256>>>(x, wq, wk, wv, (float*)d_out);
}